// round 4
// baseline (speedup 1.0000x reference)
#include <cuda_runtime.h>

#define N_NODES 100000
#define N_EDGES 1600000
#define EPT 8                     // edges per thread in edge kernels
#define NT  (N_EDGES / EPT)       // 200000 threads

// Scratch (__device__ globals; no allocation allowed)
__device__ float  g_deg[N_NODES];
__device__ float  g_dis[N_NODES];
__device__ float2 g_y[N_NODES];        // y[n] = dis[n] * x[n]
__device__ float2 g_agg[N_NODES];      // layer-1 raw scatter target
__device__ float  g_t[N_NODES];        // t[n] = dis[n] * s[n]

// v2 float reduction (one L2 sector instead of two)
__device__ __forceinline__ void red_add_v2(float2* addr, float a, float b) {
    asm volatile("red.global.add.v2.f32 [%0], {%1, %2};"
                 :: "l"(addr), "f"(a), "f"(b) : "memory");
}

// ---------------------------------------------------------------------------
// K1: degree of target nodes (8 edges/thread, 2x int4 stream)
__global__ void __launch_bounds__(256) k_deg(const int4* __restrict__ col4) {
    int i = blockIdx.x * blockDim.x + threadIdx.x;
    if (i < NT) {
        int4 c0 = col4[2 * i];
        int4 c1 = col4[2 * i + 1];
        atomicAdd(&g_deg[c0.x], 1.0f);
        atomicAdd(&g_deg[c0.y], 1.0f);
        atomicAdd(&g_deg[c0.z], 1.0f);
        atomicAdd(&g_deg[c0.w], 1.0f);
        atomicAdd(&g_deg[c1.x], 1.0f);
        atomicAdd(&g_deg[c1.y], 1.0f);
        atomicAdd(&g_deg[c1.z], 1.0f);
        atomicAdd(&g_deg[c1.w], 1.0f);
    }
}

// K2: dis = deg^-1/2 (0 if deg==0);  y[n] = dis[n]*x[n]
__global__ void __launch_bounds__(256) k_dis(const float* __restrict__ x) {
    int n = blockIdx.x * blockDim.x + threadIdx.x;
    if (n < N_NODES) {
        float d   = g_deg[n];
        float dis = (d > 0.0f) ? rsqrtf(d) : 0.0f;
        g_dis[n]  = dis;
        float2 xv = ((const float2*)x)[n];
        g_y[n]    = make_float2(dis * xv.x, dis * xv.y);
    }
}

// K3: layer-1 edge scatter: agg_raw[c] += y[r]  (8 edges/thread, batched gathers)
__global__ void __launch_bounds__(256) k_edge1(const int4* __restrict__ row4,
                                               const int4* __restrict__ col4) {
    int i = blockIdx.x * blockDim.x + threadIdx.x;
    if (i < NT) {
        int4 r0 = row4[2 * i];
        int4 r1 = row4[2 * i + 1];
        int4 c0 = col4[2 * i];
        int4 c1 = col4[2 * i + 1];
        // batch all gathers (max MLP) ...
        float2 y0 = g_y[r0.x];
        float2 y1 = g_y[r0.y];
        float2 y2 = g_y[r0.z];
        float2 y3 = g_y[r0.w];
        float2 y4 = g_y[r1.x];
        float2 y5 = g_y[r1.y];
        float2 y6 = g_y[r1.z];
        float2 y7 = g_y[r1.w];
        // ... then fire all reductions
        red_add_v2(&g_agg[c0.x], y0.x, y0.y);
        red_add_v2(&g_agg[c0.y], y1.x, y1.y);
        red_add_v2(&g_agg[c0.z], y2.x, y2.y);
        red_add_v2(&g_agg[c0.w], y3.x, y3.y);
        red_add_v2(&g_agg[c1.x], y4.x, y4.y);
        red_add_v2(&g_agg[c1.y], y5.x, y5.y);
        red_add_v2(&g_agg[c1.z], y6.x, y6.y);
        red_add_v2(&g_agg[c1.w], y7.x, y7.y);
    }
}

// K4: per-node MLP middle:
//   a = dis[n]*agg_raw[n];  s = sum_f relu(a@W1 + b1)*W2;  t[n] = dis[n]*s
__global__ void __launch_bounds__(256) k_nodemid(const float* __restrict__ W1,
                                                 const float* __restrict__ b1,
                                                 const float* __restrict__ W2) {
    __shared__ float sW1a[64], sW1b[64], sb1[64], sW2[64];
    int t = threadIdx.x;
    if (t < 64) {
        sW1a[t] = W1[t];        // W1[0][f]
        sW1b[t] = W1[64 + t];   // W1[1][f]
        sb1[t]  = b1[t];
        sW2[t]  = W2[t];
    }
    __syncthreads();
    int n = blockIdx.x * blockDim.x + t;
    if (n < N_NODES) {
        float dis = g_dis[n];
        float2 ar = g_agg[n];
        float a0 = dis * ar.x;
        float a1 = dis * ar.y;
        float s = 0.0f;
#pragma unroll
        for (int f = 0; f < 64; f++) {
            float h = fmaf(a1, sW1b[f], fmaf(a0, sW1a[f], sb1[f]));
            s = fmaf(fmaxf(h, 0.0f), sW2[f], s);
        }
        g_t[n] = dis * s;
    }
}

// K5: layer-2 edge scatter: out_raw[c] += t[r]  (8 edges/thread)
__global__ void __launch_bounds__(256) k_edge2(const int4* __restrict__ row4,
                                               const int4* __restrict__ col4,
                                               float* __restrict__ out) {
    int i = blockIdx.x * blockDim.x + threadIdx.x;
    if (i < NT) {
        int4 r0 = row4[2 * i];
        int4 r1 = row4[2 * i + 1];
        int4 c0 = col4[2 * i];
        int4 c1 = col4[2 * i + 1];
        float t0 = g_t[r0.x];
        float t1 = g_t[r0.y];
        float t2 = g_t[r0.z];
        float t3 = g_t[r0.w];
        float t4 = g_t[r1.x];
        float t5 = g_t[r1.y];
        float t6 = g_t[r1.z];
        float t7 = g_t[r1.w];
        atomicAdd(&out[c0.x], t0);
        atomicAdd(&out[c0.y], t1);
        atomicAdd(&out[c0.z], t2);
        atomicAdd(&out[c0.w], t3);
        atomicAdd(&out[c1.x], t4);
        atomicAdd(&out[c1.y], t5);
        atomicAdd(&out[c1.z], t6);
        atomicAdd(&out[c1.w], t7);
    }
}

// K6: out = relu(dis[n]*out_raw + b2)
__global__ void __launch_bounds__(256) k_final(float* __restrict__ out,
                                               const float* __restrict__ b2) {
    int n = blockIdx.x * blockDim.x + threadIdx.x;
    if (n < N_NODES) {
        out[n] = fmaxf(fmaf(g_dis[n], out[n], b2[0]), 0.0f);
    }
}

// ---------------------------------------------------------------------------
extern "C" void kernel_launch(void* const* d_in, const int* in_sizes, int n_in,
                              void* d_out, int out_size) {
    const float* x  = (const float*)d_in[0];   // [N,2] f32
    const int*   ei = (const int*)d_in[1];     // [2,E] int32 (JAX x64 off)
    const float* W1 = (const float*)d_in[2];   // [2,64]
    const float* b1 = (const float*)d_in[3];   // [64]
    const float* W2 = (const float*)d_in[4];   // [64,1]
    const float* b2 = (const float*)d_in[5];   // [1]
    float*       out = (float*)d_out;          // [N,1]

    const int4* row4 = (const int4*)ei;               // source
    const int4* col4 = (const int4*)(ei + N_EDGES);   // target

    // Zeroing via memset nodes (graph-capturable; no allocation)
    void* p_deg = nullptr;
    void* p_agg = nullptr;
    cudaGetSymbolAddress(&p_deg, g_deg);
    cudaGetSymbolAddress(&p_agg, g_agg);
    cudaMemsetAsync(p_deg, 0, N_NODES * sizeof(float));
    cudaMemsetAsync(p_agg, 0, N_NODES * sizeof(float2));
    cudaMemsetAsync(out,   0, N_NODES * sizeof(float));

    const int BT = 256;
    const int nodeBlocks = (N_NODES + BT - 1) / BT;
    const int edgeBlocks = (NT + BT - 1) / BT;

    k_deg    <<<edgeBlocks, BT>>>(col4);
    k_dis    <<<nodeBlocks, BT>>>(x);
    k_edge1  <<<edgeBlocks, BT>>>(row4, col4);
    k_nodemid<<<nodeBlocks, BT>>>(W1, b1, W2);
    k_edge2  <<<edgeBlocks, BT>>>(row4, col4, out);
    k_final  <<<nodeBlocks, BT>>>(out, b2);
}

// round 5
// speedup vs baseline: 1.0954x; 1.0954x over previous
#include <cuda_runtime.h>

#define N_NODES 100000
#define N_EDGES 1600000

// Scratch (__device__ globals; no allocation allowed)
__device__ float  g_deg[N_NODES];
__device__ float  g_dis[N_NODES];
__device__ float2 g_y[N_NODES];        // y[n] = dis[n] * x[n]
__device__ float2 g_agg[N_NODES];      // layer-1 raw scatter target
__device__ float  g_t[N_NODES];        // t[n] = dis[n] * s[n]

// v2 float reduction (one L2 sector instead of two)
__device__ __forceinline__ void red_add_v2(float2* addr, float a, float b) {
    asm volatile("red.global.add.v2.f32 [%0], {%1, %2};"
                 :: "l"(addr), "f"(a), "f"(b) : "memory");
}

// ---------------------------------------------------------------------------
// K0: zero deg, agg, out  (single fused kernel — cheaper than 3 memset nodes)
__global__ void __launch_bounds__(256) k_zero(float* __restrict__ out) {
    int i = blockIdx.x * blockDim.x + threadIdx.x;
    if (i < N_NODES) {
        g_deg[i] = 0.0f;
        g_agg[i] = make_float2(0.0f, 0.0f);
        out[i]   = 0.0f;
    }
}

// K1: degree of target nodes (4 edges/thread, int4 stream)
__global__ void __launch_bounds__(256) k_deg(const int4* __restrict__ col4) {
    int i = blockIdx.x * blockDim.x + threadIdx.x;
    if (i < N_EDGES / 4) {
        int4 c = col4[i];
        atomicAdd(&g_deg[c.x], 1.0f);
        atomicAdd(&g_deg[c.y], 1.0f);
        atomicAdd(&g_deg[c.z], 1.0f);
        atomicAdd(&g_deg[c.w], 1.0f);
    }
}

// K2: dis = deg^-1/2 (0 if deg==0);  y[n] = dis[n]*x[n]
__global__ void __launch_bounds__(256) k_dis(const float* __restrict__ x) {
    int n = blockIdx.x * blockDim.x + threadIdx.x;
    if (n < N_NODES) {
        float d   = g_deg[n];
        float dis = (d > 0.0f) ? rsqrtf(d) : 0.0f;
        g_dis[n]  = dis;
        float2 xv = ((const float2*)x)[n];
        g_y[n]    = make_float2(dis * xv.x, dis * xv.y);
    }
}

// K3: layer-1 edge scatter: agg_raw[c] += y[r]  (4 edges/thread, batched gathers)
__global__ void __launch_bounds__(256) k_edge1(const int4* __restrict__ row4,
                                               const int4* __restrict__ col4) {
    int i = blockIdx.x * blockDim.x + threadIdx.x;
    if (i < N_EDGES / 4) {
        int4 r = row4[i];
        int4 c = col4[i];
        float2 y0 = g_y[r.x];
        float2 y1 = g_y[r.y];
        float2 y2 = g_y[r.z];
        float2 y3 = g_y[r.w];
        red_add_v2(&g_agg[c.x], y0.x, y0.y);
        red_add_v2(&g_agg[c.y], y1.x, y1.y);
        red_add_v2(&g_agg[c.z], y2.x, y2.y);
        red_add_v2(&g_agg[c.w], y3.x, y3.y);
    }
}

// K4: per-node MLP middle (4 independent accumulators -> short dep chains)
//   a = dis[n]*agg_raw[n];  s = sum_f relu(a@W1 + b1)*W2;  t[n] = dis[n]*s
__global__ void __launch_bounds__(256) k_nodemid(const float* __restrict__ W1,
                                                 const float* __restrict__ b1,
                                                 const float* __restrict__ W2) {
    __shared__ float sW1a[64], sW1b[64], sb1[64], sW2[64];
    int t = threadIdx.x;
    if (t < 64) {
        sW1a[t] = W1[t];        // W1[0][f]
        sW1b[t] = W1[64 + t];   // W1[1][f]
        sb1[t]  = b1[t];
        sW2[t]  = W2[t];
    }
    __syncthreads();
    int n = blockIdx.x * blockDim.x + t;
    if (n < N_NODES) {
        float dis = g_dis[n];
        float2 ar = g_agg[n];
        float a0 = dis * ar.x;
        float a1 = dis * ar.y;
        float s0 = 0.0f, s1 = 0.0f, s2 = 0.0f, s3 = 0.0f;
#pragma unroll
        for (int f = 0; f < 64; f += 4) {
            float h0 = fmaf(a1, sW1b[f + 0], fmaf(a0, sW1a[f + 0], sb1[f + 0]));
            float h1 = fmaf(a1, sW1b[f + 1], fmaf(a0, sW1a[f + 1], sb1[f + 1]));
            float h2 = fmaf(a1, sW1b[f + 2], fmaf(a0, sW1a[f + 2], sb1[f + 2]));
            float h3 = fmaf(a1, sW1b[f + 3], fmaf(a0, sW1a[f + 3], sb1[f + 3]));
            s0 = fmaf(fmaxf(h0, 0.0f), sW2[f + 0], s0);
            s1 = fmaf(fmaxf(h1, 0.0f), sW2[f + 1], s1);
            s2 = fmaf(fmaxf(h2, 0.0f), sW2[f + 2], s2);
            s3 = fmaf(fmaxf(h3, 0.0f), sW2[f + 3], s3);
        }
        g_t[n] = dis * ((s0 + s1) + (s2 + s3));
    }
}

// K5: layer-2 edge scatter: out_raw[c] += t[r]  (4 edges/thread)
__global__ void __launch_bounds__(256) k_edge2(const int4* __restrict__ row4,
                                               const int4* __restrict__ col4,
                                               float* __restrict__ out) {
    int i = blockIdx.x * blockDim.x + threadIdx.x;
    if (i < N_EDGES / 4) {
        int4 r = row4[i];
        int4 c = col4[i];
        float t0 = g_t[r.x];
        float t1 = g_t[r.y];
        float t2 = g_t[r.z];
        float t3 = g_t[r.w];
        atomicAdd(&out[c.x], t0);
        atomicAdd(&out[c.y], t1);
        atomicAdd(&out[c.z], t2);
        atomicAdd(&out[c.w], t3);
    }
}

// K6: out = relu(dis[n]*out_raw + b2)
__global__ void __launch_bounds__(256) k_final(float* __restrict__ out,
                                               const float* __restrict__ b2) {
    int n = blockIdx.x * blockDim.x + threadIdx.x;
    if (n < N_NODES) {
        out[n] = fmaxf(fmaf(g_dis[n], out[n], b2[0]), 0.0f);
    }
}

// ---------------------------------------------------------------------------
extern "C" void kernel_launch(void* const* d_in, const int* in_sizes, int n_in,
                              void* d_out, int out_size) {
    const float* x  = (const float*)d_in[0];   // [N,2] f32
    const int*   ei = (const int*)d_in[1];     // [2,E] int32 (JAX x64 off)
    const float* W1 = (const float*)d_in[2];   // [2,64]
    const float* b1 = (const float*)d_in[3];   // [64]
    const float* W2 = (const float*)d_in[4];   // [64,1]
    const float* b2 = (const float*)d_in[5];   // [1]
    float*       out = (float*)d_out;          // [N,1]

    const int4* row4 = (const int4*)ei;               // source
    const int4* col4 = (const int4*)(ei + N_EDGES);   // target

    const int BT = 256;
    const int nodeBlocks  = (N_NODES + BT - 1) / BT;
    const int edgeBlocks4 = (N_EDGES / 4 + BT - 1) / BT;

    k_zero   <<<nodeBlocks, BT>>>(out);
    k_deg    <<<edgeBlocks4, BT>>>(col4);
    k_dis    <<<nodeBlocks, BT>>>(x);
    k_edge1  <<<edgeBlocks4, BT>>>(row4, col4);
    k_nodemid<<<nodeBlocks, BT>>>(W1, b1, W2);
    k_edge2  <<<edgeBlocks4, BT>>>(row4, col4, out);
    k_final  <<<nodeBlocks, BT>>>(out, b2);
}